// round 8
// baseline (speedup 1.0000x reference)
#include <cuda_runtime.h>

// Problem dims (fixed by reference)
#define T0_R 8192
#define T0_C 4096
#define T1_R 4096
#define T1_C 2048
#define NG   1024
#define NMAP 512
#define CAP  128       // max rows/group; Binomial(8192,1/1024) max ~25, CAP=128 safe
#define ATILE 4        // column tiles per group in k_obsA (1024 cols each)
#define BSPLIT 4       // split-K factor for obsB dot products
#define LOSSC_BLKS 16  // extra blocks in k_obsB computing loss_c

// -------- device scratch (allocation-free, self-cleaning) --------
// Statically zero-init at load; invariant: every kernel_launch call both
// begins and ends with d_cnt/d_p2/d_m1/d_loss zeroed.
//   d_cnt  : zeroed by k_final (after all obsA tiles consumed it)
//   d_p2   : zeroed by k_obsB loss_c blocks (after consumption)
//   d_m1   : zeroed by k_final (after consumption)
//   d_loss : zeroed by k_final (after consumption)
//   d_p1, d_lst : fully overwritten each call
__device__ float  d_p2[T0_C];
__device__ float  d_p1[T1_R];
__device__ float  d_m1[NMAP];
__device__ int    d_cnt[NG];
__device__ int    d_lst[NG * CAP];
__device__ double d_loss[2];       // [0]=sumsq loss_a, [1]=sumsq loss_c

// -------- block reduction (sum), result valid on thread 0 --------
__device__ __forceinline__ float block_reduce_sum(float v) {
    __shared__ float s[32];
    int lane = threadIdx.x & 31;
    int wid  = threadIdx.x >> 5;
    #pragma unroll
    for (int o = 16; o > 0; o >>= 1) v += __shfl_down_sync(0xffffffffu, v, o);
    if (lane == 0) s[wid] = v;
    __syncthreads();
    int nw = blockDim.x >> 5;
    v = (threadIdx.x < nw) ? s[threadIdx.x] : 0.0f;
    if (wid == 0) {
        #pragma unroll
        for (int o = 16; o > 0; o >>= 1) v += __shfl_down_sync(0xffffffffu, v, o);
    }
    return v;
}

__device__ __forceinline__ float exp4_sum_into(float4 v, float4& acc) {
    acc.x += __expf(v.x); acc.y += __expf(v.y);
    acc.z += __expf(v.z); acc.w += __expf(v.w);
    return 0.0f;
}

// -------- 1) build per-group row lists (idx0 int32; d_cnt arrives zeroed) ----
__global__ void k_build(const int* __restrict__ idx0, int n_idx) {
    int i = blockIdx.x * blockDim.x + threadIdx.x;
    if (i < T0_R && i < n_idx) {
        int g = idx0[i];
        if (g < 0) g = 0;
        if (g >= NG) g = NG - 1;          // defensive clamp: no OOB ever
        int slot = atomicAdd(&d_cnt[g], 1);
        if (slot < CAP) d_lst[g * CAP + slot] = i;
    }
}

// -------- 2) obsA: (group, col-tile) units, float4, row-batched -------------
// grid = NG*ATILE. unit u: g = u & 1023, tile = u >> 10. Each CTA: cnt rows x
// 1024 cols; thread t owns one float4 (cols c0+4t..c0+4t+3). Rows processed in
// batches of 4 -> 4 independent LDG.128 in flight per thread.
__global__ void __launch_bounds__(256) k_obsA(const float* __restrict__ theta0,
                                              const float* __restrict__ obs0) {
    int u = blockIdx.x;
    int g = u & (NG - 1);
    int tile = u >> 10;
    int t = threadIdx.x;

    int cnt = d_cnt[g];
    if (cnt > CAP) cnt = CAP;
    const int* rows = &d_lst[g * CAP];

    // float4 row stride = T0_C/4 = 1024; tile offset = tile*256 float4s
    const float4* base = (const float4*)theta0 + (size_t)tile * 256 + t;

    float4 acc = make_float4(0.f, 0.f, 0.f, 0.f);
    int j = 0;
    for (; j + 4 <= cnt; j += 4) {
        int r0 = rows[j], r1 = rows[j + 1], r2 = rows[j + 2], r3 = rows[j + 3];
        float4 v0 = base[(size_t)r0 * 1024];
        float4 v1 = base[(size_t)r1 * 1024];
        float4 v2 = base[(size_t)r2 * 1024];
        float4 v3 = base[(size_t)r3 * 1024];
        exp4_sum_into(v0, acc); exp4_sum_into(v1, acc);
        exp4_sum_into(v2, acc); exp4_sum_into(v3, acc);
    }
    for (; j < cnt; j++) {
        float4 v = base[(size_t)rows[j] * 1024];
        exp4_sum_into(v, acc);
    }

    // p2 contribution + loss_a partial
    int c = tile * 1024 + t * 4;
    atomicAdd(&d_p2[c + 0], acc.x);
    atomicAdd(&d_p2[c + 1], acc.y);
    atomicAdd(&d_p2[c + 2], acc.z);
    atomicAdd(&d_p2[c + 3], acc.w);

    const float4* orow = (const float4*)(obs0 + (size_t)g * T0_C) + tile * 256 + t;
    float4 o = *orow;
    float dx = o.x - acc.x, dy = o.y - acc.y, dz = o.z - acc.z, dw = o.w - acc.w;
    float tot = block_reduce_sum(dx * dx + dy * dy + dz * dz + dw * dw);
    if (t == 0) atomicAdd(&d_loss[0], (double)tot);
}

// -------- 3) p1 = rowsum of exp(theta1). grid=T1_R, 128 threads, 4xfloat4 --
__global__ void __launch_bounds__(128) k_p1(const float* __restrict__ theta1) {
    int r = blockIdx.x;
    int t = threadIdx.x;
    const float4* tr = (const float4*)(theta1 + (size_t)r * T1_C);
    float4 v0 = tr[t];
    float4 v1 = tr[t + 128];
    float4 v2 = tr[t + 256];
    float4 v3 = tr[t + 384];
    float local =
        __expf(v0.x) + __expf(v0.y) + __expf(v0.z) + __expf(v0.w) +
        __expf(v1.x) + __expf(v1.y) + __expf(v1.z) + __expf(v1.w) +
        __expf(v2.x) + __expf(v2.y) + __expf(v2.z) + __expf(v2.w) +
        __expf(v3.x) + __expf(v3.y) + __expf(v3.z) + __expf(v3.w);
    float tot = block_reduce_sum(local);
    if (t == 0) d_p1[r] = tot;
}

// -------- 4) obsB: split-K partial dots -> d_m1; tail blocks do loss_c ------
// blocks [0, NMAP*BSPLIT): b -> row o=b>>2, quarter q=b&3 (1024 cols).
// blocks [NMAP*BSPLIT, +16): loss_c slices over d_p2 + self-clean.
__global__ void __launch_bounds__(256) k_obsB(const float* __restrict__ mapping1,
                                              const float* __restrict__ obs2) {
    int b = blockIdx.x;
    int t = threadIdx.x;
    if (b < NMAP * BSPLIT) {
        int o = b >> 2;
        int q = b & 3;
        const float4* mrow = (const float4*)(mapping1 + (size_t)o * T1_R) + q * 256 + t;
        const float4* p1v  = (const float4*)d_p1 + q * 256 + t;
        float4 m = *mrow;
        float4 p = *p1v;
        float local = m.x * p.x + m.y * p.y + m.z * p.z + m.w * p.w;
        float tot = block_reduce_sum(local);
        if (t == 0) atomicAdd(&d_m1[o], tot);
    } else {
        // loss_c slice: 256 cols per block
        int c = (b - NMAP * BSPLIT) * 256 + t;
        float diff = obs2[c] - d_p2[c];
        d_p2[c] = 0.0f;                   // self-clean for next call
        float tot = block_reduce_sum(diff * diff);
        if (t == 0) atomicAdd(&d_loss[1], (double)tot);
    }
}

// -------- 5) final: loss_b from d_m1, combine, re-zero scratch --------------
__global__ void __launch_bounds__(256) k_final(const float* __restrict__ obs1,
                                               float* __restrict__ out) {
    int t = threadIdx.x;
    // loss_b: 512 entries, 2 per thread; self-clean d_m1
    float local = 0.0f;
    #pragma unroll
    for (int i = 0; i < NMAP / 256; i++) {
        int c = t + i * 256;
        float diff = obs1[c] - d_m1[c];
        local += diff * diff;
        d_m1[c] = 0.0f;
    }
    // zero d_cnt for next call (all obsA tiles finished reading it)
    #pragma unroll
    for (int i = 0; i < NG / 256; i++) d_cnt[t + i * 256] = 0;

    float sumsq_b = block_reduce_sum(local);
    if (t == 0) {
        double loss_a = d_loss[0] / ((double)NG * (double)T0_C);
        double loss_b = (double)sumsq_b / (double)NMAP;
        double loss_c = 0.5 * (d_loss[1] / (double)T0_C);
        out[0] = (float)((loss_a + loss_b + loss_c) / 3.0);
        d_loss[0] = 0.0;                  // self-clean for next call
        d_loss[1] = 0.0;
    }
}

extern "C" void kernel_launch(void* const* d_in, const int* in_sizes, int n_in,
                              void* d_out, int out_size) {
    const float* theta0   = (const float*)d_in[0];
    const float* theta1   = (const float*)d_in[1];
    const float* obs0     = (const float*)d_in[2];
    const float* obs1     = (const float*)d_in[3];
    const float* obs2     = (const float*)d_in[4];
    const int*   idx0     = (const int*)d_in[5];   // int32: JAX x64 disabled
    const float* mapping1 = (const float*)d_in[6];
    float* out = (float*)d_out;

    k_build<<<(T0_R + 255) / 256, 256>>>(idx0, in_sizes[5]);
    k_obsA<<<NG * ATILE, 256>>>(theta0, obs0);
    k_p1<<<T1_R, 128>>>(theta1);
    k_obsB<<<NMAP * BSPLIT + LOSSC_BLKS, 256>>>(mapping1, obs2);
    k_final<<<1, 256>>>(obs1, out);
}

// round 9
// speedup vs baseline: 2.4824x; 2.4824x over previous
#include <cuda_runtime.h>

// Problem dims (fixed by reference)
#define T0_R 8192
#define T0_C 4096
#define T1_R 4096
#define T1_C 2048
#define NG   1024
#define NMAP 512
#define CAP  128       // max rows/group; Binomial(8192,1/1024) max ~25, CAP=128 safe
#define ATILE 4        // column tiles per group in k_obsA (1024 cols each)
#define LOSSC_BLKS 16  // extra blocks in k_obsB computing loss_c

// -------- device scratch (allocation-free, self-cleaning) --------
// Statically zero-init at load; invariant: every kernel_launch call both
// begins and ends with d_cnt/d_p2/d_loss zeroed.
//   d_cnt  : zeroed by k_final (after all obsA tiles consumed it)
//   d_p2   : zeroed by k_obsB loss_c blocks (after consumption)
//   d_loss : zeroed by k_final (after consumption)
//   d_p1, d_lst : fully overwritten each call
__device__ float  d_p2[T0_C];
__device__ float  d_p1[T1_R];
__device__ int    d_cnt[NG];
__device__ int    d_lst[NG * CAP];
__device__ double d_loss[3];       // [0]=sumsq loss_a, [1]=sumsq loss_b, [2]=sumsq loss_c

// -------- block reduction (sum), result valid on thread 0 --------
__device__ __forceinline__ float block_reduce_sum(float v) {
    __shared__ float s[32];
    int lane = threadIdx.x & 31;
    int wid  = threadIdx.x >> 5;
    #pragma unroll
    for (int o = 16; o > 0; o >>= 1) v += __shfl_down_sync(0xffffffffu, v, o);
    if (lane == 0) s[wid] = v;
    __syncthreads();
    int nw = blockDim.x >> 5;
    v = (threadIdx.x < nw) ? s[threadIdx.x] : 0.0f;
    if (wid == 0) {
        #pragma unroll
        for (int o = 16; o > 0; o >>= 1) v += __shfl_down_sync(0xffffffffu, v, o);
    }
    return v;
}

// -------- 1) build per-group row lists (idx0 int32; d_cnt arrives zeroed) ----
__global__ void k_build(const int* __restrict__ idx0, int n_idx) {
    int i = blockIdx.x * blockDim.x + threadIdx.x;
    if (i < T0_R && i < n_idx) {
        int g = idx0[i];
        if (g < 0) g = 0;
        if (g >= NG) g = NG - 1;          // defensive clamp: no OOB ever
        int slot = atomicAdd(&d_cnt[g], 1);
        if (slot < CAP) d_lst[g * CAP + slot] = i;
    }
}

// -------- 2) obsA: (group, col-tile) units, SCALAR loads, 2-row batch -------
// grid = NG*ATILE. unit u: g = u & 1023, tile = u >> 10. Each CTA: cnt rows x
// 1024 cols; thread t owns cols c0+t+{0,256,512,768}. Rows in batches of 2 ->
// 8 independent LDG.32 in flight (cross-LDG L1tex wavefronts @1.0cyc; LDG.128
// within-LDG replays @2.07cyc were the R8 regression).
__global__ void __launch_bounds__(256) k_obsA(const float* __restrict__ theta0,
                                              const float* __restrict__ obs0) {
    int u = blockIdx.x;
    int g = u & (NG - 1);
    int tile = u >> 10;
    int t = threadIdx.x;
    int c0 = tile * 1024;

    int cnt = d_cnt[g];
    if (cnt > CAP) cnt = CAP;
    const int* rows = &d_lst[g * CAP];

    float acc[4];
    #pragma unroll
    for (int i = 0; i < 4; i++) acc[i] = 0.0f;

    int j = 0;
    for (; j + 2 <= cnt; j += 2) {
        int r0 = rows[j], r1 = rows[j + 1];
        const float* t0 = theta0 + (size_t)r0 * T0_C + c0 + t;
        const float* t1 = theta0 + (size_t)r1 * T0_C + c0 + t;
        float v[8];
        #pragma unroll
        for (int i = 0; i < 4; i++) v[i]     = __ldcs(t0 + i * 256);
        #pragma unroll
        for (int i = 0; i < 4; i++) v[4 + i] = __ldcs(t1 + i * 256);
        #pragma unroll
        for (int i = 0; i < 4; i++) acc[i] += __expf(v[i]) + __expf(v[4 + i]);
    }
    if (j < cnt) {
        int r = rows[j];
        const float* t0 = theta0 + (size_t)r * T0_C + c0 + t;
        float v[4];
        #pragma unroll
        for (int i = 0; i < 4; i++) v[i] = __ldcs(t0 + i * 256);
        #pragma unroll
        for (int i = 0; i < 4; i++) acc[i] += __expf(v[i]);
    }

    const float* orow = obs0 + (size_t)g * T0_C + c0;
    float local = 0.0f;
    #pragma unroll
    for (int i = 0; i < 4; i++) {
        int c = t + i * 256;
        atomicAdd(&d_p2[c0 + c], acc[i]);
        float diff = orow[c] - acc[i];
        local += diff * diff;
    }
    float tot = block_reduce_sum(local);
    if (t == 0) atomicAdd(&d_loss[0], (double)tot);
}

// -------- 3) p1 = rowsum of exp(theta1). grid=T1_R, 256 thr, 8 batched LDG --
__global__ void __launch_bounds__(256) k_p1(const float* __restrict__ theta1) {
    int r = blockIdx.x;
    int t = threadIdx.x;
    const float* tr = theta1 + (size_t)r * T1_C + t;
    float v[8];
    #pragma unroll
    for (int i = 0; i < 8; i++) v[i] = __ldcs(tr + i * 256);
    float local = 0.0f;
    #pragma unroll
    for (int i = 0; i < 8; i++) local += __expf(v[i]);
    float tot = block_reduce_sum(local);
    if (t == 0) d_p1[r] = tot;
}

// -------- 4) obsB: blocks [0,NMAP) = mapping1 @ p1 + loss_b; ---------------
//            blocks [NMAP, NMAP+16) = loss_c slices + d_p2 self-clean
__global__ void __launch_bounds__(256) k_obsB(const float* __restrict__ mapping1,
                                              const float* __restrict__ obs1,
                                              const float* __restrict__ obs2) {
    int b = blockIdx.x;
    int t = threadIdx.x;
    if (b < NMAP) {
        const float* mrow = mapping1 + (size_t)b * T1_R + t;
        float m[16], p[16];
        #pragma unroll
        for (int i = 0; i < 16; i++) m[i] = __ldcs(mrow + i * 256);
        #pragma unroll
        for (int i = 0; i < 16; i++) p[i] = d_p1[t + i * 256];
        float local = 0.0f;
        #pragma unroll
        for (int i = 0; i < 16; i++) local += m[i] * p[i];
        float tot = block_reduce_sum(local);
        if (t == 0) {
            float diff = obs1[b] - tot;
            atomicAdd(&d_loss[1], (double)(diff * diff));
        }
    } else {
        // loss_c slice: 256 cols per block
        int c = (b - NMAP) * 256 + t;
        float diff = obs2[c] - d_p2[c];
        d_p2[c] = 0.0f;                   // self-clean for next call
        float tot = block_reduce_sum(diff * diff);
        if (t == 0) atomicAdd(&d_loss[2], (double)tot);
    }
}

// -------- 5) final combine + scratch re-zero. 1 block, 256 threads ---------
__global__ void __launch_bounds__(256) k_final(float* __restrict__ out) {
    int t = threadIdx.x;
    // zero d_cnt for next call (all obsA tiles finished reading it)
    #pragma unroll
    for (int i = 0; i < NG / 256; i++) d_cnt[t + i * 256] = 0;
    if (t == 0) {
        double loss_a = d_loss[0] / ((double)NG * (double)T0_C);
        double loss_b = d_loss[1] / (double)NMAP;
        double loss_c = 0.5 * (d_loss[2] / (double)T0_C);
        out[0] = (float)((loss_a + loss_b + loss_c) / 3.0);
        d_loss[0] = 0.0;                  // self-clean for next call
        d_loss[1] = 0.0;
        d_loss[2] = 0.0;
    }
}

extern "C" void kernel_launch(void* const* d_in, const int* in_sizes, int n_in,
                              void* d_out, int out_size) {
    const float* theta0   = (const float*)d_in[0];
    const float* theta1   = (const float*)d_in[1];
    const float* obs0     = (const float*)d_in[2];
    const float* obs1     = (const float*)d_in[3];
    const float* obs2     = (const float*)d_in[4];
    const int*   idx0     = (const int*)d_in[5];   // int32: JAX x64 disabled
    const float* mapping1 = (const float*)d_in[6];
    float* out = (float*)d_out;

    k_build<<<(T0_R + 255) / 256, 256>>>(idx0, in_sizes[5]);
    k_obsA<<<NG * ATILE, 256>>>(theta0, obs0);
    k_p1<<<T1_R, 256>>>(theta1);
    k_obsB<<<NMAP + LOSSC_BLKS, 256>>>(mapping1, obs1, obs2);
    k_final<<<1, 256>>>(out);
}